// round 2
// baseline (speedup 1.0000x reference)
#include <cuda_runtime.h>
#include <cstdint>

#define LGRID 512
#define BATCH 32768
#define TPB   32
#define NBLK  (BATCH / 2 / TPB)   // 16384 threads -> 512 blocks

typedef unsigned long long ull;

// packed f32x2 ops (sm_103a FFMA2/FMUL2/FADD2 — PTX-only)
#define FMA2(d, a, b, c) asm("fma.rn.f32x2 %0, %1, %2, %3;" : "=l"(d) : "l"(a), "l"(b), "l"(c))
#define MUL2(d, a, b)    asm("mul.rn.f32x2 %0, %1, %2;"     : "=l"(d) : "l"(a), "l"(b))
#define ADD2(d, a, b)    asm("add.rn.f32x2 %0, %1, %2;"     : "=l"(d) : "l"(a), "l"(b))

__device__ __forceinline__ ull pack2(float lo, float hi) {
    ull r;
    asm("mov.b64 %0, {%1, %2};" : "=l"(r) : "r"(__float_as_uint(lo)), "r"(__float_as_uint(hi)));
    return r;
}

__global__ __launch_bounds__(TPB)
void ode_euler2_kernel(const float* __restrict__ s_grid,
                       const float* __restrict__ y0,
                       const float* __restrict__ w,
                       float* __restrict__ out) {
    __shared__ ull sh_h[LGRID - 1];

    const int tid = threadIdx.x;

    // pre-pack step sizes (h, h) once; broadcast reads later
    for (int j = tid; j < LGRID - 1; j += TPB) {
        const float h = s_grid[j + 1] - s_grid[j];
        sh_h[j] = pack2(h, h);
    }
    __syncthreads();

    // broadcast-pack the 21 weights
    ull W0, W1, W2, W3, W4, W5, W6, W7, W8, W9, W10,
        W11, W12, W13, W14, W15, W16, W17, W18, W19, W20;
    {
        float t;
        t = __ldg(w + 0);  W0  = pack2(t, t);
        t = __ldg(w + 1);  W1  = pack2(t, t);
        t = __ldg(w + 2);  W2  = pack2(t, t);
        t = __ldg(w + 3);  W3  = pack2(t, t);
        t = __ldg(w + 4);  W4  = pack2(t, t);
        t = __ldg(w + 5);  W5  = pack2(t, t);
        t = __ldg(w + 6);  W6  = pack2(t, t);
        t = __ldg(w + 7);  W7  = pack2(t, t);
        t = __ldg(w + 8);  W8  = pack2(t, t);
        t = __ldg(w + 9);  W9  = pack2(t, t);
        t = __ldg(w + 10); W10 = pack2(t, t);
        t = __ldg(w + 11); W11 = pack2(t, t);
        t = __ldg(w + 12); W12 = pack2(t, t);
        t = __ldg(w + 13); W13 = pack2(t, t);
        t = __ldg(w + 14); W14 = pack2(t, t);
        t = __ldg(w + 15); W15 = pack2(t, t);
        t = __ldg(w + 16); W16 = pack2(t, t);
        t = __ldg(w + 17); W17 = pack2(t, t);
        t = __ldg(w + 18); W18 = pack2(t, t);
        t = __ldg(w + 19); W19 = pack2(t, t);
        t = __ldg(w + 20); W20 = pack2(t, t);
    }

    // this thread owns trajectories (2g, 2g+1)
    const int g = blockIdx.x * TPB + tid;   // 0 .. BATCH/2-1
    const ull* y0v = (const ull*)y0;
    ull* outv = (ull*)out;

    const int HB = BATCH / 2;

    ull A = y0v[0 * HB + g];
    ull T = y0v[1 * HB + g];
    ull N = y0v[2 * HB + g];
    ull C = y0v[3 * HB + g];

    // emit y0
    outv[0 * HB + g] = A;
    outv[1 * HB + g] = T;
    outv[2 * HB + g] = N;
    outv[3 * HB + g] = C;

    #pragma unroll 4
    for (int i = 0; i < LGRID - 1; ++i) {
        const ull h = sh_h[i];

        ull A2, T2, N2, C2, AT, TN, NC;
        MUL2(A2, A, A);
        MUL2(T2, T, T);
        MUL2(N2, N, N);
        MUL2(C2, C, C);
        MUL2(AT, A, T);
        MUL2(TN, T, N);
        MUL2(NC, N, C);

        // dA = w0 + w1*A + w2*A2
        ull dA;
        FMA2(dA, W1, A, W0);
        FMA2(dA, W2, A2, dA);

        // dT = (w3 + w4*T + w5*T2) + (w6*A + w7*A2 + w8*AT)   [balanced tree]
        ull tl, tr, dT;
        FMA2(tl, W4, T, W3);
        FMA2(tl, W5, T2, tl);
        MUL2(tr, W6, A);
        FMA2(tr, W8, AT, tr);
        FMA2(tr, W7, A2, tr);
        ADD2(dT, tl, tr);

        // dN = (w9 + w10*N + w11*N2) + (w12*T + w13*T2 + w14*TN)
        ull nl, nr, dN;
        FMA2(nl, W10, N, W9);
        FMA2(nl, W11, N2, nl);
        MUL2(nr, W12, T);
        FMA2(nr, W14, TN, nr);
        FMA2(nr, W13, T2, nr);
        ADD2(dN, nl, nr);

        // dC = (w15 + w16*C + w17*C2) + (w18*N + w19*N2 + w20*NC)
        ull cl, cr, dC;
        FMA2(cl, W16, C, W15);
        FMA2(cl, W17, C2, cl);
        MUL2(cr, W18, N);
        FMA2(cr, W20, NC, cr);
        FMA2(cr, W19, N2, cr);
        ADD2(dC, cl, cr);

        FMA2(A, h, dA, A);
        FMA2(T, h, dT, T);
        FMA2(N, h, dN, N);
        FMA2(C, h, dC, C);

        ull* o = outv + (size_t)(i + 1) * (4 * HB) + g;
        o[0 * HB] = A;
        o[1 * HB] = T;
        o[2 * HB] = N;
        o[3 * HB] = C;
    }
}

extern "C" void kernel_launch(void* const* d_in, const int* in_sizes, int n_in,
                              void* d_out, int out_size) {
    const float* s_grid = (const float*)d_in[0];
    const float* y0     = (const float*)d_in[1];
    const float* w      = (const float*)d_in[2];
    float* out          = (float*)d_out;

    ode_euler2_kernel<<<NBLK, TPB>>>(s_grid, y0, w, out);
}

// round 3
// speedup vs baseline: 1.1101x; 1.1101x over previous
#include <cuda_runtime.h>
#include <cstdint>

#define LGRID 512
#define BATCH 32768
#define TPB   64
#define NBLK  (BATCH / TPB)   // 512 blocks, 1024 warps total

typedef unsigned long long ull;

// packed f32x2 ops (sm_103a FFMA2/FMUL2/FADD2 — PTX-only)
#define FMA2(d, a, b, c) asm("fma.rn.f32x2 %0, %1, %2, %3;" : "=l"(d) : "l"(a), "l"(b), "l"(c))
#define MUL2(d, a, b)    asm("mul.rn.f32x2 %0, %1, %2;"     : "=l"(d) : "l"(a), "l"(b))
#define ADD2(d, a, b)    asm("add.rn.f32x2 %0, %1, %2;"     : "=l"(d) : "l"(a), "l"(b))

__device__ __forceinline__ ull pack2(float lo, float hi) {
    ull r;
    asm("mov.b64 %0, {%1, %2};" : "=l"(r) : "f"(lo), "f"(hi));
    return r;
}
__device__ __forceinline__ void unpack2(ull v, float& lo, float& hi) {
    asm("mov.b64 {%0, %1}, %2;" : "=f"(lo), "=f"(hi) : "l"(v));
}

__global__ __launch_bounds__(TPB)
void ode_euler3_kernel(const float* __restrict__ s_grid,
                       const float* __restrict__ y0,
                       const float* __restrict__ w,
                       float* __restrict__ out) {
    __shared__ ull sh_h[LGRID - 1];

    const int tid = threadIdx.x;

    // pre-pack step sizes (h, h); broadcast LDS.64 later
    for (int j = tid; j < LGRID - 1; j += TPB) {
        const float h = s_grid[j + 1] - s_grid[j];
        sh_h[j] = pack2(h, h);
    }
    __syncthreads();

    // packed weight pairs: lane-lo drives dA/dN, lane-hi drives dT/dC
    const ull W03    = pack2(__ldg(w + 0),  __ldg(w + 3));
    const ull W14    = pack2(__ldg(w + 1),  __ldg(w + 4));
    const ull W25    = pack2(__ldg(w + 2),  __ldg(w + 5));
    const ull W_6    = pack2(0.0f,          __ldg(w + 6));
    const ull W_7    = pack2(0.0f,          __ldg(w + 7));
    const ull W_8    = pack2(0.0f,          __ldg(w + 8));
    const ull W9_15  = pack2(__ldg(w + 9),  __ldg(w + 15));
    const ull W10_16 = pack2(__ldg(w + 10), __ldg(w + 16));
    const ull W11_17 = pack2(__ldg(w + 11), __ldg(w + 17));
    const ull W12_18 = pack2(__ldg(w + 12), __ldg(w + 18));
    const ull W13_19 = pack2(__ldg(w + 13), __ldg(w + 19));
    const ull W14_20 = pack2(__ldg(w + 14), __ldg(w + 20));

    const int b = blockIdx.x * TPB + tid;   // one trajectory per thread

    float A = y0[0 * BATCH + b];
    float T = y0[1 * BATCH + b];
    float N = y0[2 * BATCH + b];
    float C = y0[3 * BATCH + b];

    // emit y0
    out[0 * BATCH + b] = A;
    out[1 * BATCH + b] = T;
    out[2 * BATCH + b] = N;
    out[3 * BATCH + b] = C;

    ull X = pack2(A, T);   // (A, T)
    ull Y = pack2(N, C);   // (N, C)

    #pragma unroll 4
    for (int i = 0; i < LGRID - 1; ++i) {
        const ull h = sh_h[i];

        const ull S1 = pack2(0.0f, A);  // cross source for dX: (-, A)
        const ull S2 = pack2(T, N);     // cross source for dY: (T, N)

        ull Xs, Ys, S1s, S2s, S1X, S2Y;
        MUL2(Xs,  X,  X);    // (A2, T2)
        MUL2(Ys,  Y,  Y);    // (N2, C2)
        MUL2(S1s, S1, S1);   // (0,  A2)
        MUL2(S2s, S2, S2);   // (T2, N2)
        MUL2(S1X, S1, X);    // (0,  A*T)
        MUL2(S2Y, S2, Y);    // (T*N, N*C)

        // dX = (w0,w3) + (w1,w4)X + (w2,w5)X^2 + (0,w6)S1 + (0,w7)S1^2 + (0,w8)S1X
        ull ax, bx, dX;
        FMA2(ax, W14, X, W03);
        FMA2(ax, W25, Xs, ax);
        MUL2(bx, W_6, S1);
        FMA2(bx, W_7, S1s, bx);
        FMA2(bx, W_8, S1X, bx);
        ADD2(dX, ax, bx);

        // dY = (w9,w15) + (w10,w16)Y + (w11,w17)Y^2 + (w12,w18)S2 + (w13,w19)S2^2 + (w14,w20)S2Y
        ull ay, by, dY;
        FMA2(ay, W10_16, Y, W9_15);
        FMA2(ay, W11_17, Ys, ay);
        MUL2(by, W12_18, S2);
        FMA2(by, W13_19, S2s, by);
        FMA2(by, W14_20, S2Y, by);
        ADD2(dY, ay, by);

        FMA2(X, h, dX, X);
        FMA2(Y, h, dY, Y);

        unpack2(X, A, T);
        unpack2(Y, N, C);

        float* o = out + (size_t)(i + 1) * (4 * BATCH) + b;
        o[0 * BATCH] = A;
        o[1 * BATCH] = T;
        o[2 * BATCH] = N;
        o[3 * BATCH] = C;
    }
}

extern "C" void kernel_launch(void* const* d_in, const int* in_sizes, int n_in,
                              void* d_out, int out_size) {
    const float* s_grid = (const float*)d_in[0];
    const float* y0     = (const float*)d_in[1];
    const float* w      = (const float*)d_in[2];
    float* out          = (float*)d_out;

    ode_euler3_kernel<<<NBLK, TPB>>>(s_grid, y0, w, out);
}